// round 6
// baseline (speedup 1.0000x reference)
#include <cuda_runtime.h>
#include <float.h>

#define KNN      8
#define THREADS  512          // 4 subgroups x 128 query-threads
#define NSPLIT   4            // M-dimension split inside the CTA
#define QPB      128          // queries per block
#define SCHUNK   512          // refs per subgroup tile (256 pairs x 32B = 8KB/subgroup)
#define PAIRS    (SCHUNK/2)
#define MGW      (NSPLIT*KNN + 1)   // merge row stride (33) -> conflict-free

#define BUFSLOTS 16           // per-thread candidate buffer (smem, 64-bit packed)
#define FLUSH_AT 9            // flush when any lane has >= 9 (max +8/group -> fits 16)

// smem layout (dynamic):
//   [0, UNION_BYTES): phase1 = u64 tile[NSPLIT][PAIRS*4]   (32KB, pair-SoA)
//                     phase2 = mgd[QPB][MGW] + mgi[QPB][MGW] (33792B)
//   [UNION_BYTES, +BUF_BYTES): u64 buf[BUFSLOTS][THREADS]
#define UNION_BYTES  (QPB * MGW * 4 * 2)              // 33792
#define BUF_BYTES    (BUFSLOTS * THREADS * 8)          // 65536
#define SMEM_TOTAL   (UNION_BYTES + BUF_BYTES)         // 99328

typedef unsigned long long u64;

__device__ __forceinline__ u64 pack2(float lo, float hi) {
    return (u64)__float_as_uint(lo) | ((u64)__float_as_uint(hi) << 32);
}
__device__ __forceinline__ u64 fma2(u64 a, u64 b, u64 c) {
    u64 d;
    asm("fma.rn.f32x2 %0, %1, %2, %3;" : "=l"(d) : "l"(a), "l"(b), "l"(c));
    return d;
}

// Streaming top-8 insertion (sorted ascending; strict < keeps earlier index on
// ties, matching jax top_k tie order).
__device__ __forceinline__ void insert8(float (&bd)[KNN], int (&bi)[KNN], float d, int id) {
#pragma unroll
    for (int k = 0; k < KNN; k++) {
        if (d < bd[k]) {
            float td = bd[k]; int ti = bi[k];
            bd[k] = d; bi[k] = id;
            d = td; id = ti;
        }
    }
}

__global__ __launch_bounds__(THREADS, 2)
void knn_idw_kernel(const float* __restrict__ qpts,
                    const float* __restrict__ rpts,
                    const float* __restrict__ rflow,
                    float* __restrict__ out,
                    int N, int M)
{
    extern __shared__ char smem_raw[];
    u64*   tile = (u64*)smem_raw;                           // [NSPLIT][PAIRS*4]
    float* mgd  = (float*)smem_raw;                         // [QPB][MGW]
    int*   mgi  = (int*)(smem_raw + QPB * MGW * 4);         // [QPB][MGW]
    u64*   buf  = (u64*)(smem_raw + UNION_BYTES);

    const int tid = threadIdx.x;
    const int sg  = tid >> 7;          // subgroup 0..3 (which M-quarter)
    const int qt  = tid & 127;         // query slot within block
    const int qi  = blockIdx.x * QPB + qt;

    float qx = 0.f, qy = 0.f, qz = 0.f;
    if (qi < N) {
        qx = qpts[3 * qi + 0];
        qy = qpts[3 * qi + 1];
        qz = qpts[3 * qi + 2];
    }
    // ranking key: s = |r|^2 - 2 q.r  (|q|^2 per-query constant, added in epilogue)
    const u64 ax2 = pack2(-2.f * qx, -2.f * qx);
    const u64 ay2 = pack2(-2.f * qy, -2.f * qy);
    const u64 az2 = pack2(-2.f * qz, -2.f * qz);

    const int Mper   = (M + NSPLIT - 1) / NSPLIT;
    const int mybase = sg * Mper;
    const int myend  = min(M, mybase + Mper);

    float bd[KNN]; int bi[KNN];
#pragma unroll
    for (int k = 0; k < KNN; k++) { bd[k] = FLT_MAX; bi[k] = 0; }
    float thr = FLT_MAX;   // stale copy of bd[7]; refreshed at flush (superset-safe)
    int nbuf = 0;

    for (int base = 0; base < Mper; base += SCHUNK) {
        const int gbase = mybase + base;
        const int cnt   = min(SCHUNK, myend - gbase);
        const int npair = cnt >> 1;                 // cnt is even for these shapes
        __syncthreads();
        // cooperative tile load, pair-SoA: (x0,x1)(y0,y1)(z0,z1)(w0,w1) u64 lanes
        for (int pp = qt; pp < npair; pp += 128) {
            const float* rp = rpts + 3 * (gbase + 2 * pp);
            float x0 = __ldg(rp + 0), y0 = __ldg(rp + 1), z0 = __ldg(rp + 2);
            float x1 = __ldg(rp + 3), y1 = __ldg(rp + 4), z1 = __ldg(rp + 5);
            float w0 = fmaf(x0, x0, fmaf(y0, y0, z0 * z0));
            float w1 = fmaf(x1, x1, fmaf(y1, y1, z1 * z1));
            u64* tp = tile + (sg * PAIRS + pp) * 4;
            tp[0] = pack2(x0, x1);
            tp[1] = pack2(y0, y1);
            tp[2] = pack2(z0, z1);
            tp[3] = pack2(w0, w1);
        }
        __syncthreads();

        const u64* __restrict__ p = tile + sg * PAIRS * 4;
        int pp = 0;
        // hot loop: 4 pairs (8 refs) per iteration
        for (; pp + 4 <= npair; pp += 4) {
#pragma unroll
            for (int u = 0; u < 4; u++) {
                const u64* tp = p + (pp + u) * 4;            // 2x LDS.128 (broadcast)
                u64 x2 = tp[0], y2 = tp[1], z2 = tp[2], w2 = tp[3];
                u64 s2 = fma2(ax2, x2, fma2(ay2, y2, fma2(az2, z2, w2)));
                float slo = __uint_as_float((unsigned)s2);
                float shi = __uint_as_float((unsigned)(s2 >> 32));
                if (fminf(slo, shi) < thr) {                 // pair-granular filter
                    const int id0 = gbase + 2 * (pp + u);
                    buf[ nbuf      * THREADS + tid] = (u64)__float_as_uint(slo) | ((u64)(unsigned)id0 << 32);
                    buf[(nbuf + 1) * THREADS + tid] = (u64)__float_as_uint(shi) | ((u64)(unsigned)(id0 + 1) << 32);
                    nbuf += 2;
                }
            }
            // warp-uniform flush decision
            if (__any_sync(0xffffffffu, nbuf >= FLUSH_AT)) {
#pragma unroll 1
                for (int t = 0; t < nbuf; t++) {
                    u64 v = buf[t * THREADS + tid];
                    float d = __uint_as_float((unsigned)v);
                    int  id = (int)(v >> 32);
                    if (d < bd[KNN - 1]) insert8(bd, bi, d, id);
                }
                nbuf = 0;
                thr = bd[KNN - 1];
            }
        }
        // pair remainder
        for (; pp < npair; pp++) {
            const u64* tp = p + pp * 4;
            u64 x2 = tp[0], y2 = tp[1], z2 = tp[2], w2 = tp[3];
            u64 s2 = fma2(ax2, x2, fma2(ay2, y2, fma2(az2, z2, w2)));
            float slo = __uint_as_float((unsigned)s2);
            float shi = __uint_as_float((unsigned)(s2 >> 32));
            int id0 = gbase + 2 * pp;
            if (slo < bd[KNN - 1]) insert8(bd, bi, slo, id0);
            if (shi < bd[KNN - 1]) insert8(bd, bi, shi, id0 + 1);
        }
        // odd-ref remainder (not taken for these shapes)
        if (cnt & 1) {
            const int j = cnt - 1;
            const float* rp = rpts + 3 * (gbase + j);
            float x = __ldg(rp + 0), y = __ldg(rp + 1), z = __ldg(rp + 2);
            float w = fmaf(x, x, fmaf(y, y, z * z));
            float sv = fmaf(-2.f * qx, x, fmaf(-2.f * qy, y, fmaf(-2.f * qz, z, w)));
            if (sv < bd[KNN - 1]) insert8(bd, bi, sv, gbase + j);
        }
    }

    // final drain of leftover buffered candidates
#pragma unroll 1
    for (int t = 0; t < nbuf; t++) {
        u64 v = buf[t * THREADS + tid];
        float d = __uint_as_float((unsigned)v);
        int  id = (int)(v >> 32);
        if (d < bd[KNN - 1]) insert8(bd, bi, d, id);
    }

    // ---- merge phase: publish 4 partial top-8 lists per query, subgroup 0 reduces ----
    __syncthreads();            // all tile reads done before union region is reused
#pragma unroll
    for (int k = 0; k < KNN; k++) {
        mgd[qt * MGW + sg * KNN + k] = bd[k];
        mgi[qt * MGW + sg * KNN + k] = bi[k];
    }
    __syncthreads();

    if (sg == 0 && qi < N) {
        float fd[KNN]; int fi[KNN];
#pragma unroll
        for (int k = 0; k < KNN; k++) { fd[k] = FLT_MAX; fi[k] = 0; }
        // ascending chunk order + strict < preserves lowest-index tie rule
#pragma unroll 4
        for (int c = 0; c < NSPLIT * KNN; c++) {
            float d = mgd[qt * MGW + c];
            if (d < fd[KNN - 1]) insert8(fd, fi, d, mgi[qt * MGW + c]);
        }

        // epilogue: d2 = s + |q|^2 (clamped), w = 1/(d2+eps)   [sqrt cancels: POWER==2]
        const float q2 = fmaf(qx, qx, fmaf(qy, qy, qz * qz));
        float sumw = 0.f, fx = 0.f, fy = 0.f, fz = 0.f;
#pragma unroll
        for (int k = 0; k < KNN; k++) {
            float d2 = fmaxf(fd[k] + q2, 0.0f);
            float w  = 1.0f / (d2 + 1e-8f);
            sumw += w;
            const float* f = rflow + 3 * fi[k];
            fx = fmaf(w, __ldg(f + 0), fx);
            fy = fmaf(w, __ldg(f + 1), fy);
            fz = fmaf(w, __ldg(f + 2), fz);
        }
        const float inv = 1.0f / sumw;
        out[3 * qi + 0] = fx * inv;
        out[3 * qi + 1] = fy * inv;
        out[3 * qi + 2] = fz * inv;
    }
}

extern "C" void kernel_launch(void* const* d_in, const int* in_sizes, int n_in,
                              void* d_out, int out_size)
{
    const float* qpts  = (const float*)d_in[0];   // [N,3] float32
    const float* rpts  = (const float*)d_in[1];   // [M,3] float32
    const float* rflow = (const float*)d_in[2];   // [M,3] float32
    float* out = (float*)d_out;                   // [N,3] float32

    const int N = in_sizes[0] / 3;
    const int M = in_sizes[1] / 3;

    cudaFuncSetAttribute(knn_idw_kernel,
                         cudaFuncAttributeMaxDynamicSharedMemorySize, SMEM_TOTAL);

    const int grid = (N + QPB - 1) / QPB;
    knn_idw_kernel<<<grid, THREADS, SMEM_TOTAL>>>(qpts, rpts, rflow, out, N, M);
}